// round 1
// baseline (speedup 1.0000x reference)
#include <cuda_runtime.h>
#include <math.h>

// Scratch: SoA param arrays for up to 65536 (view,gaussian) entries.
// params: 0=z, 1=u, 2=v, 3=ia, 4=ib, 5=idd, 6=op, 7=cr, 8=cg, 9=cb, 10=rad
#define CAP (1 << 16)
#define NPARAM 11
__device__ float g_raw[NPARAM][CAP];
__device__ float g_srt[NPARAM][CAP];

// ---------------------------------------------------------------------------
// Phase 1: per-(view, gaussian) preprocessing
// ---------------------------------------------------------------------------
__global__ void prep_kernel(const float* __restrict__ means,
                            const float* __restrict__ scales,
                            const float* __restrict__ rots,
                            const float* __restrict__ sh,
                            const float* __restrict__ opac,
                            const float* __restrict__ extr,
                            const float* __restrict__ intr,
                            const int* __restrict__ Hp,
                            const int* __restrict__ Wp,
                            int G, int NV)
{
    int i = blockIdx.x * blockDim.x + threadIdx.x;
    if (i >= G * NV) return;
    int vi = i / G;
    int g  = i - vi * G;

    float Wf = (float)(*Wp), Hf = (float)(*Hp);
    const float* E = extr + vi * 16;   // 4x4 row-major
    const float* K = intr + vi * 9;    // 3x3 row-major
    // reference divides by [[W,W,W],[H,H,H],[1,1,1]] then re-multiplies
    float fx = (K[0] / Wf) * Wf;
    float cx = (K[2] / Wf) * Wf;
    float fy = (K[4] / Hf) * Hf;
    float cy = (K[5] / Hf) * Hf;

    float mx = means[g*3+0], my = means[g*3+1], mz = means[g*3+2];
    float px = E[0]*mx + E[1]*my + E[2]*mz  + E[3];
    float py = E[4]*mx + E[5]*my + E[6]*mz  + E[7];
    float pz = E[8]*mx + E[9]*my + E[10]*mz + E[11];
    float zs = fmaxf(pz, 1e-6f);
    float u = fx * px / zs + cx;
    float v = fy * py / zs + cy;

    // quaternion (w,x,y,z) -> rotation
    float qw = rots[g*4+0], qx = rots[g*4+1], qy = rots[g*4+2], qz = rots[g*4+3];
    float qinv = rsqrtf(qw*qw + qx*qx + qy*qy + qz*qz);
    qw *= qinv; qx *= qinv; qy *= qinv; qz *= qinv;
    float R00 = 1.f - 2.f*(qy*qy + qz*qz), R01 = 2.f*(qx*qy - qw*qz), R02 = 2.f*(qx*qz + qw*qy);
    float R10 = 2.f*(qx*qy + qw*qz), R11 = 1.f - 2.f*(qx*qx + qz*qz), R12 = 2.f*(qy*qz - qw*qx);
    float R20 = 2.f*(qx*qz - qw*qy), R21 = 2.f*(qy*qz + qw*qx), R22 = 1.f - 2.f*(qx*qx + qy*qy);

    float s0 = scales[g*3+0], s1 = scales[g*3+1], s2 = scales[g*3+2];
    float M00=R00*s0, M01=R01*s1, M02=R02*s2;
    float M10=R10*s0, M11=R11*s1, M12=R12*s2;
    float M20=R20*s0, M21=R21*s1, M22=R22*s2;
    float S00 = M00*M00+M01*M01+M02*M02;
    float S01 = M00*M10+M01*M11+M02*M12;
    float S02 = M00*M20+M01*M21+M02*M22;
    float S11 = M10*M10+M11*M11+M12*M12;
    float S12 = M10*M20+M11*M21+M12*M22;
    float S22 = M20*M20+M21*M21+M22*M22;

    float iz  = 1.f / zs;
    float J00 = fx*iz,  J02 = -fx*px*iz*iz;
    float J11 = fy*iz,  J12 = -fy*py*iz*iz;
    // T3 = J @ Rcw
    float t00 = J00*E[0] + J02*E[8];
    float t01 = J00*E[1] + J02*E[9];
    float t02 = J00*E[2] + J02*E[10];
    float t10 = J11*E[4] + J12*E[8];
    float t11 = J11*E[5] + J12*E[9];
    float t12 = J11*E[6] + J12*E[10];
    // cov2D = T3 Sigma T3^T + 0.3 I
    float w0 = S00*t00 + S01*t01 + S02*t02;
    float w1 = S01*t00 + S11*t01 + S12*t02;
    float w2 = S02*t00 + S12*t01 + S22*t02;
    float a  = t00*w0 + t01*w1 + t02*w2 + 0.3f;
    float b  = t10*w0 + t11*w1 + t12*w2;
    float x0 = S00*t10 + S01*t11 + S02*t12;
    float x1 = S01*t10 + S11*t11 + S12*t12;
    float x2 = S02*t10 + S12*t11 + S22*t12;
    float d  = t10*x0 + t11*x1 + t12*x2 + 0.3f;

    float det = a*d - b*b;
    float ds  = fmaxf(det, 1e-12f);
    float ia = d/ds, ib = -b/ds, idd = a/ds;
    bool valid = (pz > 0.2f) && (det > 1e-12f);
    float op = valid ? opac[g] : 0.f;

    const float SH_C0 = 0.28209479177387814f;
    float cr = fmaxf(SH_C0 * sh[g*3+0] + 0.5f, 0.f);
    float cg = fmaxf(SH_C0 * sh[g*3+1] + 0.5f, 0.f);
    float cb = fmaxf(SH_C0 * sh[g*3+2] + 0.5f, 0.f);

    // Conservative cull radius: alpha >= 1/255 requires
    // 0.5*d^T C d <= ln(255*op); with 0.5*lmin(C)|d|^2 lower bound and
    // lmin(C) = 1/lmax(cov2D) (valid => cov2D SPD): |d| <= sqrt(2 ln(255 op) lmax)
    float rad = -1.f;
    if (op * 255.f > 1.f) {
        float lam = 0.5f*(a+d) + sqrtf(0.25f*(a-d)*(a-d) + b*b);
        float t = logf(255.f * op);
        rad = sqrtf(fmaxf(2.f*t*lam, 0.f)) + 0.05f;  // small fp safety margin
    }

    int o = vi*G + g;
    g_raw[0][o]=pz;  g_raw[1][o]=u;   g_raw[2][o]=v;  g_raw[3][o]=ia;
    g_raw[4][o]=ib;  g_raw[5][o]=idd; g_raw[6][o]=op; g_raw[7][o]=cr;
    g_raw[8][o]=cg;  g_raw[9][o]=cb;  g_raw[10][o]=rad;
}

// ---------------------------------------------------------------------------
// Phase 2: per-view bitonic sort by depth + gather into sorted SoA
// ---------------------------------------------------------------------------
#define SORT_CAP 4096
__global__ void sort_kernel(int G)
{
    __shared__ float key[SORT_CAP];
    __shared__ unsigned short val[SORT_CAP];
    int vi = blockIdx.x;
    int tid = threadIdx.x;
    int np2 = 1; while (np2 < G) np2 <<= 1;

    for (int i = tid; i < np2; i += blockDim.x) {
        key[i] = (i < G) ? g_raw[0][vi*G + i] : 3.4e38f;
        val[i] = (unsigned short)i;
    }
    __syncthreads();
    for (int k = 2; k <= np2; k <<= 1) {
        for (int j = k >> 1; j > 0; j >>= 1) {
            for (int i = tid; i < np2; i += blockDim.x) {
                int ixj = i ^ j;
                if (ixj > i) {
                    bool up = ((i & k) == 0);
                    float ki = key[i], kj = key[ixj];
                    if ((ki > kj) == up) {
                        key[i] = kj; key[ixj] = ki;
                        unsigned short t = val[i]; val[i] = val[ixj]; val[ixj] = t;
                    }
                }
            }
            __syncthreads();
        }
    }
    for (int i = tid; i < G; i += blockDim.x) {
        int src = vi*G + (int)val[i];
        int dst = vi*G + i;
        #pragma unroll
        for (int c = 0; c < NPARAM; c++) g_srt[c][dst] = g_raw[c][src];
    }
}

// ---------------------------------------------------------------------------
// Phase 3: tiled front-to-back compositing. 16x16 pixel tile per block,
// one pixel per thread. Chunked order-preserving stream compaction of the
// sorted gaussian list into shared memory, then sequential alpha blend.
// ---------------------------------------------------------------------------
__global__ void composite_kernel(float* __restrict__ out,
                                 const int* __restrict__ Hp,
                                 const int* __restrict__ Wp,
                                 int G)
{
    const int TS = 16;
    int W = *Wp, H = *Hp;
    int ntx = (W + TS - 1) / TS, nty = (H + TS - 1) / TS;
    int tile = blockIdx.x;
    int vi = blockIdx.y;
    if (tile >= ntx * nty) return;
    int tx = tile % ntx, ty = tile / ntx;
    int tid = threadIdx.x;
    int lane = tid & 31, wid = tid >> 5;
    int lx = tid & 15, ly = tid >> 4;
    int px = tx*TS + lx, py = ty*TS + ly;
    bool inb = (px < W) && (py < H);
    float pcx = px + 0.5f, pcy = py + 0.5f;
    float tminx = (float)(tx*TS),     tmaxx = (float)(tx*TS + TS);
    float tminy = (float)(ty*TS),     tmaxy = (float)(ty*TS + TS);

    __shared__ float s_u[256], s_v[256], s_ia[256], s_ib[256], s_id[256];
    __shared__ float s_op[256], s_cr[256], s_cg[256], s_cb[256], s_z[256];
    __shared__ int s_wcnt[8];

    float T = 1.f, accr = 0.f, accg = 0.f, accb = 0.f, accd = 0.f;
    int base = vi * G;

    for (int c0 = 0; c0 < G; c0 += 256) {
        int gi = c0 + tid;
        bool keep = false;
        float u=0, v=0, ia=0, ib=0, idd=0, op=0, cr=0, cg=0, cb=0, z=0;
        if (gi < G) {
            float rad = g_srt[10][base+gi];
            if (rad > 0.f) {
                u = g_srt[1][base+gi]; v = g_srt[2][base+gi];
                if (u >= tminx - rad && u <= tmaxx + rad &&
                    v >= tminy - rad && v <= tmaxy + rad) {
                    keep = true;
                    ia = g_srt[3][base+gi]; ib = g_srt[4][base+gi];
                    idd= g_srt[5][base+gi]; op = g_srt[6][base+gi];
                    cr = g_srt[7][base+gi]; cg = g_srt[8][base+gi];
                    cb = g_srt[9][base+gi]; z  = g_srt[0][base+gi];
                }
            }
        }
        // order-preserving block compaction (ballot + warp-count scan)
        unsigned bal = __ballot_sync(0xffffffffu, keep);
        int lpre = __popc(bal & ((1u << lane) - 1u));
        if (lane == 0) s_wcnt[wid] = __popc(bal);
        __syncthreads();
        int off = 0, tot = 0;
        #pragma unroll
        for (int w = 0; w < 8; w++) {
            int c = s_wcnt[w];
            if (w < wid) off += c;
            tot += c;
        }
        if (keep) {
            int p = off + lpre;
            s_u[p]=u; s_v[p]=v; s_ia[p]=ia; s_ib[p]=ib; s_id[p]=idd;
            s_op[p]=op; s_cr[p]=cr; s_cg[p]=cg; s_cb[p]=cb; s_z[p]=z;
        }
        __syncthreads();

        if (T > 1e-4f) {   // early-out: residual contribution bounded by T
            for (int j = 0; j < tot; j++) {
                float du = pcx - s_u[j], dv = pcy - s_v[j];
                float power = -0.5f*(s_ia[j]*du*du + s_id[j]*dv*dv) - s_ib[j]*du*dv;
                power = fminf(power, 0.f);
                float alpha = fminf(s_op[j] * expf(power), 0.99f);
                if (alpha >= (1.0f/255.0f)) {
                    float w = alpha * T;
                    accr += w * s_cr[j]; accg += w * s_cg[j]; accb += w * s_cb[j];
                    accd += w * s_z[j];
                    T *= (1.f - alpha);
                }
            }
        }
        __syncthreads();
    }

    if (inb) {
        int o = ((vi * H + py) * W + px) * 4;
        out[o+0] = accr; out[o+1] = accg; out[o+2] = accb; out[o+3] = accd;
    }
}

// ---------------------------------------------------------------------------
extern "C" void kernel_launch(void* const* d_in, const int* in_sizes, int n_in,
                              void* d_out, int out_size)
{
    const float* means  = (const float*)d_in[0];
    const float* scales = (const float*)d_in[1];
    const float* rots   = (const float*)d_in[2];
    const float* sh     = (const float*)d_in[3];
    const float* opac   = (const float*)d_in[4];
    const float* extr   = (const float*)d_in[5];
    const float* intr   = (const float*)d_in[6];
    const int*   Hp     = (const int*)d_in[7];
    const int*   Wp     = (const int*)d_in[8];
    float* out = (float*)d_out;

    int G  = in_sizes[4];        // B = 1 for this problem instance
    int NV = in_sizes[5] / 16;   // B*N views
    int HW = out_size / (4 * NV);

    int total = G * NV;
    prep_kernel<<<(total + 255) / 256, 256>>>(means, scales, rots, sh, opac,
                                              extr, intr, Hp, Wp, G, NV);
    sort_kernel<<<NV, 1024>>>(G);

    // H,W live on device; over-provision tile grid and bail in-kernel.
    // ceil(W/16)*ceil(H/16) <= (16*HW + 240)/256 + 1 for any W,H >= 1.
    int maxTiles = (16 * HW + 240) / 256 + 1;
    dim3 grid(maxTiles, NV);
    composite_kernel<<<grid, 256>>>(out, Hp, Wp, G);
}

// round 2
// speedup vs baseline: 1.9177x; 1.9177x over previous
#include <cuda_runtime.h>
#include <math.h>

// Scratch SoA (float4-packed) for up to 16384 (view,gaussian) entries.
#define CAP (1 << 14)
__device__ float4 g_cull[CAP];   // (u, v, rad, z)
__device__ float4 g_con[CAP];    // (ia, ib, idd, op)
__device__ float4 g_col[CAP];    // (cr, cg, cb, 0)

// ---------------------------------------------------------------------------
// Phase 1: per-(view, gaussian) preprocessing
// ---------------------------------------------------------------------------
__global__ void prep_kernel(const float* __restrict__ means,
                            const float* __restrict__ scales,
                            const float* __restrict__ rots,
                            const float* __restrict__ sh,
                            const float* __restrict__ opac,
                            const float* __restrict__ extr,
                            const float* __restrict__ intr,
                            const int* __restrict__ Hp,
                            const int* __restrict__ Wp,
                            int G, int NV)
{
    int i = blockIdx.x * blockDim.x + threadIdx.x;
    if (i >= G * NV) return;
    int vi = i / G;
    int g  = i - vi * G;

    float Wf = (float)(*Wp), Hf = (float)(*Hp);
    const float* E = extr + vi * 16;   // 4x4 row-major
    const float* K = intr + vi * 9;    // 3x3 row-major
    float fx = (K[0] / Wf) * Wf;
    float cx = (K[2] / Wf) * Wf;
    float fy = (K[4] / Hf) * Hf;
    float cy = (K[5] / Hf) * Hf;

    float mx = means[g*3+0], my = means[g*3+1], mz = means[g*3+2];
    float px = E[0]*mx + E[1]*my + E[2]*mz  + E[3];
    float py = E[4]*mx + E[5]*my + E[6]*mz  + E[7];
    float pz = E[8]*mx + E[9]*my + E[10]*mz + E[11];
    float zs = fmaxf(pz, 1e-6f);
    float u = fx * px / zs + cx;
    float v = fy * py / zs + cy;

    float qw = rots[g*4+0], qx = rots[g*4+1], qy = rots[g*4+2], qz = rots[g*4+3];
    float qinv = rsqrtf(qw*qw + qx*qx + qy*qy + qz*qz);
    qw *= qinv; qx *= qinv; qy *= qinv; qz *= qinv;
    float R00 = 1.f - 2.f*(qy*qy + qz*qz), R01 = 2.f*(qx*qy - qw*qz), R02 = 2.f*(qx*qz + qw*qy);
    float R10 = 2.f*(qx*qy + qw*qz), R11 = 1.f - 2.f*(qx*qx + qz*qz), R12 = 2.f*(qy*qz - qw*qx);
    float R20 = 2.f*(qx*qz - qw*qy), R21 = 2.f*(qy*qz + qw*qx), R22 = 1.f - 2.f*(qx*qx + qy*qy);

    float s0 = scales[g*3+0], s1 = scales[g*3+1], s2 = scales[g*3+2];
    float M00=R00*s0, M01=R01*s1, M02=R02*s2;
    float M10=R10*s0, M11=R11*s1, M12=R12*s2;
    float M20=R20*s0, M21=R21*s1, M22=R22*s2;
    float S00 = M00*M00+M01*M01+M02*M02;
    float S01 = M00*M10+M01*M11+M02*M12;
    float S02 = M00*M20+M01*M21+M02*M22;
    float S11 = M10*M10+M11*M11+M12*M12;
    float S12 = M10*M20+M11*M21+M12*M22;
    float S22 = M20*M20+M21*M21+M22*M22;

    float iz  = 1.f / zs;
    float J00 = fx*iz,  J02 = -fx*px*iz*iz;
    float J11 = fy*iz,  J12 = -fy*py*iz*iz;
    float t00 = J00*E[0] + J02*E[8];
    float t01 = J00*E[1] + J02*E[9];
    float t02 = J00*E[2] + J02*E[10];
    float t10 = J11*E[4] + J12*E[8];
    float t11 = J11*E[5] + J12*E[9];
    float t12 = J11*E[6] + J12*E[10];
    float w0 = S00*t00 + S01*t01 + S02*t02;
    float w1 = S01*t00 + S11*t01 + S12*t02;
    float w2 = S02*t00 + S12*t01 + S22*t02;
    float a  = t00*w0 + t01*w1 + t02*w2 + 0.3f;
    float b  = t10*w0 + t11*w1 + t12*w2;
    float x0 = S00*t10 + S01*t11 + S02*t12;
    float x1 = S01*t10 + S11*t11 + S12*t12;
    float x2 = S02*t10 + S12*t11 + S22*t12;
    float d  = t10*x0 + t11*x1 + t12*x2 + 0.3f;

    float det = a*d - b*b;
    float ds  = fmaxf(det, 1e-12f);
    float ia = d/ds, ib = -b/ds, idd = a/ds;
    bool valid = (pz > 0.2f) && (det > 1e-12f);
    float op = valid ? opac[g] : 0.f;

    const float SH_C0 = 0.28209479177387814f;
    float cr = fmaxf(SH_C0 * sh[g*3+0] + 0.5f, 0.f);
    float cg = fmaxf(SH_C0 * sh[g*3+1] + 0.5f, 0.f);
    float cb = fmaxf(SH_C0 * sh[g*3+2] + 0.5f, 0.f);

    // Conservative cull radius: alpha >= 1/255 needs 0.5 d^T C d <= ln(255 op);
    // bound via lmin(C)=1/lmax(cov2D): |d| <= sqrt(2 ln(255 op) lmax(cov2D)).
    float rad = -1.f;
    if (op * 255.f > 1.f) {
        float lam = 0.5f*(a+d) + sqrtf(0.25f*(a-d)*(a-d) + b*b);
        float t = logf(255.f * op);
        rad = sqrtf(fmaxf(2.f*t*lam, 0.f)) + 0.05f;
    }

    int o = vi*G + g;
    g_cull[o] = make_float4(u, v, rad, pz);
    g_con[o]  = make_float4(ia, ib, idd, op);
    g_col[o]  = make_float4(cr, cg, cb, 0.f);
}

// ---------------------------------------------------------------------------
// Phase 2: per-tile cull + per-tile depth sort + front-to-back compositing.
// 16x16 pixel tile per block, one pixel per thread.
// ---------------------------------------------------------------------------
#define MAXK 2048   // >= G for this problem

__global__ void composite_kernel(float* __restrict__ out,
                                 const int* __restrict__ Hp,
                                 const int* __restrict__ Wp,
                                 int G)
{
    const int TS = 16;
    int W = *Wp, H = *Hp;
    int ntx = (W + TS - 1) / TS, nty = (H + TS - 1) / TS;
    int tile = blockIdx.x;
    int vi = blockIdx.y;
    if (tile >= ntx * nty) return;
    int tx = tile % ntx, ty = tile / ntx;
    int tid = threadIdx.x;
    int lx = tid & 15, ly = tid >> 4;
    int px = tx*TS + lx, py = ty*TS + ly;
    bool inb = (px < W) && (py < H);
    float pcx = px + 0.5f, pcy = py + 0.5f;
    float tminx = (float)(tx*TS), tmaxx = (float)(tx*TS + TS);
    float tminy = (float)(ty*TS), tmaxy = (float)(ty*TS + TS);

    __shared__ unsigned long long s_key[MAXK];
    __shared__ float4 s_uvz[256];   // (u, v, rad, z)
    __shared__ float4 s_con[256];   // (ia, ib, idd, op)
    __shared__ float4 s_col[256];   // (cr, cg, cb, 0)
    __shared__ int s_cnt;

    if (tid == 0) s_cnt = 0;
    __syncthreads();

    int base = vi * G;

    // ---- cull: append survivors as packed (flipped z bits, index) keys ----
    for (int gi = tid; gi < G; gi += 256) {
        float4 c = g_cull[base + gi];
        if (c.z > 0.f &&
            c.x >= tminx - c.z && c.x <= tmaxx + c.z &&
            c.y >= tminy - c.z && c.y <= tmaxy + c.z) {
            unsigned int zb = __float_as_uint(c.w);
            zb = (zb & 0x80000000u) ? ~zb : (zb | 0x80000000u);
            int p = atomicAdd(&s_cnt, 1);
            s_key[p] = ((unsigned long long)zb << 32) | (unsigned int)gi;
        }
    }
    __syncthreads();
    int cnt = s_cnt;

    // ---- per-tile bitonic sort (stable via index in low bits) ----
    if (cnt > 1) {
        int m = 1; while (m < cnt) m <<= 1;
        for (int i = cnt + tid; i < m; i += 256) s_key[i] = ~0ull;
        __syncthreads();
        for (int k = 2; k <= m; k <<= 1) {
            for (int j = k >> 1; j > 0; j >>= 1) {
                for (int i = tid; i < m; i += 256) {
                    int ixj = i ^ j;
                    if (ixj > i) {
                        bool up = ((i & k) == 0);
                        unsigned long long a = s_key[i], b = s_key[ixj];
                        if ((a > b) == up) { s_key[i] = b; s_key[ixj] = a; }
                    }
                }
                __syncthreads();
            }
        }
    }

    // ---- blend in sorted order, staged in chunks of 256 ----
    float T = 1.f, accr = 0.f, accg = 0.f, accb = 0.f, accd = 0.f;
    for (int c0 = 0; c0 < cnt; c0 += 256) {
        int e = c0 + tid;
        if (e < cnt) {
            int idx = base + (int)(unsigned int)s_key[e];
            s_uvz[tid] = g_cull[idx];
            s_con[tid] = g_con[idx];
            s_col[tid] = g_col[idx];
        }
        __syncthreads();
        int n = min(256, cnt - c0);
        if (T > 1e-4f) {
            for (int j = 0; j < n; j++) {
                float4 uvz = s_uvz[j];
                float4 con = s_con[j];
                float du = pcx - uvz.x, dv = pcy - uvz.y;
                float power = -0.5f*(con.x*du*du + con.z*dv*dv) - con.y*du*dv;
                power = fminf(power, 0.f);
                float alpha = fminf(con.w * expf(power), 0.99f);
                if (alpha >= (1.0f/255.0f)) {
                    float4 col = s_col[j];
                    float w = alpha * T;
                    accr += w * col.x; accg += w * col.y; accb += w * col.z;
                    accd += w * uvz.w;
                    T *= (1.f - alpha);
                }
            }
        }
        // barrier + whole-tile early-out in one op
        if (__syncthreads_and(T <= 1e-4f)) break;
    }

    if (inb) {
        int o = ((vi * H + py) * W + px) * 4;
        out[o+0] = accr; out[o+1] = accg; out[o+2] = accb; out[o+3] = accd;
    }
}

// ---------------------------------------------------------------------------
extern "C" void kernel_launch(void* const* d_in, const int* in_sizes, int n_in,
                              void* d_out, int out_size)
{
    const float* means  = (const float*)d_in[0];
    const float* scales = (const float*)d_in[1];
    const float* rots   = (const float*)d_in[2];
    const float* sh     = (const float*)d_in[3];
    const float* opac   = (const float*)d_in[4];
    const float* extr   = (const float*)d_in[5];
    const float* intr   = (const float*)d_in[6];
    const int*   Hp     = (const int*)d_in[7];
    const int*   Wp     = (const int*)d_in[8];
    float* out = (float*)d_out;

    int G  = in_sizes[4];        // B = 1 for this instance
    int NV = in_sizes[5] / 16;   // B*N views
    int HW = out_size / (4 * NV);

    int total = G * NV;
    prep_kernel<<<(total + 255) / 256, 256>>>(means, scales, rots, sh, opac,
                                              extr, intr, Hp, Wp, G, NV);

    // H,W live on device; over-provision tile grid, bail in-kernel.
    int maxTiles = (16 * HW + 240) / 256 + 1;
    dim3 grid(maxTiles, NV);
    composite_kernel<<<grid, 256>>>(out, Hp, Wp, G);
}

// round 3
// speedup vs baseline: 2.8099x; 1.4652x over previous
#include <cuda_runtime.h>
#include <math.h>

// Scratch SoA (float4-packed) for up to 16384 (view,gaussian) entries.
#define CAP (1 << 14)
__device__ float4 g_cull[CAP];   // (u, v, rad, z)
__device__ float4 g_con[CAP];    // (ia, ib, idd, op)
__device__ float4 g_col[CAP];    // (cr, cg, cb, powThresh)

// ---------------------------------------------------------------------------
// Phase 1: per-(view, gaussian) preprocessing
// ---------------------------------------------------------------------------
__global__ void prep_kernel(const float* __restrict__ means,
                            const float* __restrict__ scales,
                            const float* __restrict__ rots,
                            const float* __restrict__ sh,
                            const float* __restrict__ opac,
                            const float* __restrict__ extr,
                            const float* __restrict__ intr,
                            const int* __restrict__ Hp,
                            const int* __restrict__ Wp,
                            int G, int NV)
{
    int i = blockIdx.x * blockDim.x + threadIdx.x;
    if (i >= G * NV) return;
    int vi = i / G;
    int g  = i - vi * G;

    float Wf = (float)(*Wp), Hf = (float)(*Hp);
    const float* E = extr + vi * 16;   // 4x4 row-major
    const float* K = intr + vi * 9;    // 3x3 row-major
    float fx = (K[0] / Wf) * Wf;
    float cx = (K[2] / Wf) * Wf;
    float fy = (K[4] / Hf) * Hf;
    float cy = (K[5] / Hf) * Hf;

    float mx = means[g*3+0], my = means[g*3+1], mz = means[g*3+2];
    float px = E[0]*mx + E[1]*my + E[2]*mz  + E[3];
    float py = E[4]*mx + E[5]*my + E[6]*mz  + E[7];
    float pz = E[8]*mx + E[9]*my + E[10]*mz + E[11];
    float zs = fmaxf(pz, 1e-6f);
    float u = fx * px / zs + cx;
    float v = fy * py / zs + cy;

    float4 q4 = ((const float4*)rots)[g];
    float qw = q4.x, qx = q4.y, qy = q4.z, qz = q4.w;
    float qinv = rsqrtf(qw*qw + qx*qx + qy*qy + qz*qz);
    qw *= qinv; qx *= qinv; qy *= qinv; qz *= qinv;
    float R00 = 1.f - 2.f*(qy*qy + qz*qz), R01 = 2.f*(qx*qy - qw*qz), R02 = 2.f*(qx*qz + qw*qy);
    float R10 = 2.f*(qx*qy + qw*qz), R11 = 1.f - 2.f*(qx*qx + qz*qz), R12 = 2.f*(qy*qz - qw*qx);
    float R20 = 2.f*(qx*qz - qw*qy), R21 = 2.f*(qy*qz + qw*qx), R22 = 1.f - 2.f*(qx*qx + qy*qy);

    float s0 = scales[g*3+0], s1 = scales[g*3+1], s2 = scales[g*3+2];
    float M00=R00*s0, M01=R01*s1, M02=R02*s2;
    float M10=R10*s0, M11=R11*s1, M12=R12*s2;
    float M20=R20*s0, M21=R21*s1, M22=R22*s2;
    float S00 = M00*M00+M01*M01+M02*M02;
    float S01 = M00*M10+M01*M11+M02*M12;
    float S02 = M00*M20+M01*M21+M02*M22;
    float S11 = M10*M10+M11*M11+M12*M12;
    float S12 = M10*M20+M11*M21+M12*M22;
    float S22 = M20*M20+M21*M21+M22*M22;

    float iz  = 1.f / zs;
    float J00 = fx*iz,  J02 = -fx*px*iz*iz;
    float J11 = fy*iz,  J12 = -fy*py*iz*iz;
    float t00 = J00*E[0] + J02*E[8];
    float t01 = J00*E[1] + J02*E[9];
    float t02 = J00*E[2] + J02*E[10];
    float t10 = J11*E[4] + J12*E[8];
    float t11 = J11*E[5] + J12*E[9];
    float t12 = J11*E[6] + J12*E[10];
    float w0 = S00*t00 + S01*t01 + S02*t02;
    float w1 = S01*t00 + S11*t01 + S12*t02;
    float w2 = S02*t00 + S12*t01 + S22*t02;
    float a  = t00*w0 + t01*w1 + t02*w2 + 0.3f;
    float b  = t10*w0 + t11*w1 + t12*w2;
    float x0 = S00*t10 + S01*t11 + S02*t12;
    float x1 = S01*t10 + S11*t11 + S12*t12;
    float x2 = S02*t10 + S12*t11 + S22*t12;
    float d  = t10*x0 + t11*x1 + t12*x2 + 0.3f;

    float det = a*d - b*b;
    float ds  = fmaxf(det, 1e-12f);
    float ia = d/ds, ib = -b/ds, idd = a/ds;
    bool valid = (pz > 0.2f) && (det > 1e-12f);
    float op = valid ? opac[g] : 0.f;

    const float SH_C0 = 0.28209479177387814f;
    float cr = fmaxf(SH_C0 * sh[g*3+0] + 0.5f, 0.f);
    float cg = fmaxf(SH_C0 * sh[g*3+1] + 0.5f, 0.f);
    float cb = fmaxf(SH_C0 * sh[g*3+2] + 0.5f, 0.f);

    // Conservative cull radius: alpha >= 1/255 needs 0.5 d^T C d <= ln(255 op);
    // bound via lmin(C)=1/lmax(cov2D): |d| <= sqrt(2 ln(255 op) lmax(cov2D)).
    float rad = -1.f;
    float thr = 0.f;
    if (op * 255.f > 1.f) {
        float lam = 0.5f*(a+d) + sqrtf(0.25f*(a-d)*(a-d) + b*b);
        float t = logf(255.f * op);
        rad = sqrtf(fmaxf(2.f*t*lam, 0.f)) + 0.05f;
        thr = -t - 1e-4f;   // power < thr  =>  alpha < 1/255 guaranteed
    }

    int o = vi*G + g;
    g_cull[o] = make_float4(u, v, rad, pz);
    g_con[o]  = make_float4(ia, ib, idd, op);
    g_col[o]  = make_float4(cr, cg, cb, thr);
}

// ---------------------------------------------------------------------------
// Phase 2: per-tile cull + sort + segment-parallel front-to-back compositing.
// 1024 threads = 4 depth segments x 256 pixels (16x16 tile).
// Grid-stride over tiles (tile count known only on device).
// ---------------------------------------------------------------------------
#define NSEG 4
#define NTHR 1024

__global__ __launch_bounds__(NTHR, 1)
void composite_kernel(float* __restrict__ out,
                      const int* __restrict__ Hp,
                      const int* __restrict__ Wp,
                      int G, int NV)
{
    const int TS = 16;
    int W = *Wp, H = *Hp;
    int ntx = (W + TS - 1) / TS, nty = (H + TS - 1) / TS;
    int totalTiles = ntx * nty * NV;

    extern __shared__ char dsm[];
    unsigned long long* s_key = (unsigned long long*)dsm;       // G * 8
    float4* s_pos = (float4*)(dsm + (size_t)G * 8);             // (u,v,thr,z)
    float4* s_con = s_pos + G;                                  // (ia,ib,idd,op)
    float4* s_col = s_con + G;                                  // (cr,cg,cb,-)
    __shared__ float4 segC[NSEG][256];
    __shared__ float  segT[NSEG][256];
    __shared__ int s_cnt;

    int tid = threadIdx.x;
    int lane = tid & 31;
    int seg = tid >> 8, pix = tid & 255;
    int lx = pix & 15, ly = pix >> 4;

    for (int tile = blockIdx.x; tile < totalTiles; tile += gridDim.x) {
        int vi = tile / (ntx * nty);
        int t2 = tile - vi * ntx * nty;
        int tx = t2 % ntx, ty = t2 / ntx;
        int base = vi * G;

        float tminx = (float)(tx*TS), tmaxx = (float)(tx*TS + TS);
        float tminy = (float)(ty*TS), tmaxy = (float)(ty*TS + TS);

        __syncthreads();
        if (tid == 0) s_cnt = 0;
        __syncthreads();

        // ---- cull: warp-aggregated append of (flipped z bits | index) ----
        for (int gi = tid; gi < G; gi += NTHR) {
            float4 c = g_cull[base + gi];
            bool keep = (c.z > 0.f &&
                         c.x >= tminx - c.z && c.x <= tmaxx + c.z &&
                         c.y >= tminy - c.z && c.y <= tmaxy + c.z);
            unsigned m = __ballot_sync(0xffffffffu, keep);
            if (m) {
                int leader = __ffs(m) - 1;
                int basep = 0;
                if (lane == leader) basep = atomicAdd(&s_cnt, __popc(m));
                basep = __shfl_sync(0xffffffffu, basep, leader);
                if (keep) {
                    unsigned int zb = __float_as_uint(c.w);
                    zb = (zb & 0x80000000u) ? ~zb : (zb | 0x80000000u);
                    int p = basep + __popc(m & ((1u << lane) - 1u));
                    s_key[p] = ((unsigned long long)zb << 32) | (unsigned int)gi;
                }
            }
        }
        __syncthreads();
        int cnt = s_cnt;

        // ---- bitonic sort (exact, stable: index in low bits) ----
        if (cnt > 1) {
            int msz = 1; while (msz < cnt) msz <<= 1;
            for (int i = cnt + tid; i < msz; i += NTHR) s_key[i] = ~0ull;
            __syncthreads();
            for (int k = 2; k <= msz; k <<= 1) {
                for (int j = k >> 1; j > 0; j >>= 1) {
                    for (int i = tid; i < msz; i += NTHR) {
                        int ixj = i ^ j;
                        if (ixj > i) {
                            bool up = ((i & k) == 0);
                            unsigned long long a = s_key[i], b = s_key[ixj];
                            if ((a > b) == up) { s_key[i] = b; s_key[ixj] = a; }
                        }
                    }
                    __syncthreads();
                }
            }
        }

        // ---- gather all survivor params into smem in sorted order ----
        for (int i = tid; i < cnt; i += NTHR) {
            int idx = base + (int)(unsigned int)s_key[i];
            float4 cu = g_cull[idx];
            float4 cl = g_col[idx];
            s_pos[i] = make_float4(cu.x, cu.y, cl.w, cu.w);
            s_con[i] = g_con[idx];
            s_col[i] = cl;
        }
        __syncthreads();

        // ---- segment-parallel blend: each segment handles cnt/NSEG entries ----
        float pcx = (float)(tx*TS + lx) + 0.5f;
        float pcy = (float)(ty*TS + ly) + 0.5f;
        int L = (cnt + NSEG - 1) / NSEG;
        int j0 = seg * L;
        int j1 = min(j0 + L, cnt);

        float T = 1.f, ar = 0.f, ag = 0.f, ab = 0.f, ad = 0.f;
        for (int j = j0; j < j1; j++) {
            float4 p  = s_pos[j];
            float4 cn = s_con[j];
            float du = pcx - p.x, dv = pcy - p.y;
            float power = -0.5f*(cn.x*du*du + cn.z*dv*dv) - cn.y*du*dv;
            if (power < p.z) continue;           // alpha < 1/255 guaranteed
            power = fminf(power, 0.f);
            float alpha = fminf(cn.w * expf(power), 0.99f);
            if (alpha >= (1.0f/255.0f)) {
                float4 cl = s_col[j];
                float w = alpha * T;
                ar += w * cl.x; ag += w * cl.y; ab += w * cl.z;
                ad += w * p.w;
                T *= (1.f - alpha);
                if (T < 1e-5f) break;            // residual < 1e-5 absolute
            }
        }
        segC[seg][pix] = make_float4(ar, ag, ab, ad);
        segT[seg][pix] = T;
        __syncthreads();

        // ---- combine segments front-to-back + store ----
        if (seg == 0) {
            float4 C = segC[0][pix];
            float Tacc = segT[0][pix];
            #pragma unroll
            for (int s = 1; s < NSEG; s++) {
                float4 Cs = segC[s][pix];
                C.x += Tacc * Cs.x; C.y += Tacc * Cs.y;
                C.z += Tacc * Cs.z; C.w += Tacc * Cs.w;
                Tacc *= segT[s][pix];
            }
            int px = tx*TS + lx, py = ty*TS + ly;
            if (px < W && py < H) {
                ((float4*)out)[(vi * H + py) * W + px] = C;
            }
        }
    }
}

// ---------------------------------------------------------------------------
extern "C" void kernel_launch(void* const* d_in, const int* in_sizes, int n_in,
                              void* d_out, int out_size)
{
    const float* means  = (const float*)d_in[0];
    const float* scales = (const float*)d_in[1];
    const float* rots   = (const float*)d_in[2];
    const float* sh     = (const float*)d_in[3];
    const float* opac   = (const float*)d_in[4];
    const float* extr   = (const float*)d_in[5];
    const float* intr   = (const float*)d_in[6];
    const int*   Hp     = (const int*)d_in[7];
    const int*   Wp     = (const int*)d_in[8];
    float* out = (float*)d_out;

    int G  = in_sizes[4];        // B = 1 for this instance
    int NV = in_sizes[5] / 16;   // B*N views

    int total = G * NV;
    prep_kernel<<<(total + 63) / 64, 64>>>(means, scales, rots, sh, opac,
                                           extr, intr, Hp, Wp, G, NV);

    size_t dynSmem = (size_t)G * (8 + 16 + 16 + 16);   // keys + pos + con + col
    static int attrSet = 0;
    if (!attrSet) {
        cudaFuncSetAttribute(composite_kernel,
                             cudaFuncAttributeMaxDynamicSharedMemorySize,
                             (int)dynSmem);
        attrSet = 1;
    }
    composite_kernel<<<296, NTHR, dynSmem>>>(out, Hp, Wp, G, NV);
}